// round 14
// baseline (speedup 1.0000x reference)
#include <cuda_runtime.h>

// AdderConv + BatchNorm2d (training stats): x[8,32,28,28], W[64,32,3,3], pad=1.
// out[n,o,h,w] = -sum_k |x - w|, then per-channel BN (biased var, eps=1e-5).
//
// SINGLE kernel. Grid (2 row-halves, 8 oc-groups, 8 n) = 128 blocks x 448 thr
// (14 warps: channel-team A = warps 0-6 -> channels 0-15, team B = warps 7-13
// -> channels 16-31). Thread = 2 horizontal pixels x 8 ocs (packed as 4 f32x2
// oc-pair accumulators per pixel). x streamed through smem in 4 phases of 4
// channels as (x,x)-duplicated u64 (32KB); w packed oc-pairs (9KB). Per (c,dr):
// 2x LDS.128 x + 6x LDS.128 w + 24 fused (FADD2,2xLOP3,FADD2). Team combine via
// smem f32x2 adds; block stats; replay-safe ticket barrier (128 co-resident
// blocks); per-channel scale/bias; in-register normalize; float2 stores.

__device__ float g_psum[64 * 16];     // [oc][pidx], pidx = n*2 + half
__device__ float g_psumsq[64 * 16];
__device__ unsigned g_ctr;            // monotonic ticket counter (never reset)

__device__ __forceinline__ void adder2(unsigned long long& acc,
                                       unsigned long long xx,
                                       unsigned long long w,
                                       unsigned long long mask) {
    asm("{\n\t"
        ".reg .b64 t;\n\t"
        "add.rn.f32x2 t, %1, %2;\n\t"
        "and.b64 t, t, %3;\n\t"
        "add.rn.f32x2 %0, %0, t;\n\t"
        "}"
        : "+l"(acc) : "l"(xx), "l"(w), "l"(mask));
}

__device__ __forceinline__ unsigned long long add_f32x2(unsigned long long a,
                                                        unsigned long long b) {
    unsigned long long r;
    asm("add.rn.f32x2 %0, %1, %2;" : "=l"(r) : "l"(a), "l"(b));
    return r;
}

__global__ __launch_bounds__(448) void fused_kernel(
    const float* __restrict__ x, const float* __restrict__ W,
    const float* __restrict__ gamma, const float* __restrict__ beta,
    float* __restrict__ out)
{
    __shared__ __align__(16) unsigned long long xt[2][4][16][32];  // 32KB dup-x
    __shared__ __align__(16) ulonglong2 nws2[288 * 2];             // 9KB w oc-pairs
    __shared__ float red[16][7];
    __shared__ float2 scb[8];

    const int half = blockIdx.x;  // 0..1: rows half*14 .. half*14+13
    const int ocg  = blockIdx.y;  // 0..7
    const int n    = blockIdx.z;  // 0..7
    const int tid  = threadIdx.x;
    const int wid  = tid >> 5;    // 0..13
    const int lid  = tid & 31;
    const int team = (wid >= 7);  // 0: ch 0-15, 1: ch 16-31
    const int wt   = wid - team * 7;
    const int lt   = tid - team * 224;      // 0..223 within team
    const bool act = (lid < 28);
    const int rloc = wt * 2 + (lid >= 14 ? 1 : 0);  // local out row 0..13
    const int c0   = (lid % 14) * 2;                // out col base (even)

    // ---- weights: nw64[k*4+p] = pack(-W[2p][k], -W[2p+1][k]) ----
    const float* Wb = W + (ocg * 8) * 288;
    unsigned long long* nw64 = (unsigned long long*)nws2;
    for (int i = tid; i < 288 * 4; i += 448) {
        int k = i >> 2, p = i & 3;
        unsigned lo = __float_as_uint(-Wb[(2 * p) * 288 + k]);
        unsigned hi = __float_as_uint(-Wb[(2 * p + 1) * 288 + k]);
        nw64[k * 4 + p] = ((unsigned long long)hi << 32) | lo;
    }

    const unsigned long long mask = 0x7FFFFFFF7FFFFFFFULL;
    unsigned long long acc[2][4];            // [px][ocpair]
    #pragma unroll
    for (int p = 0; p < 2; ++p)
        #pragma unroll
        for (int j = 0; j < 4; ++j) acc[p][j] = 0ull;

    const int prow0 = half * 14;             // first padded row in tile

    // ---- 4 phases of 4 channels per team ----
    #pragma unroll 1
    for (int ph = 0; ph < 4; ++ph) {
        const int cb = team * 16 + ph * 4;   // absolute channel base
        __syncthreads();                     // previous compute done
        const float* xb = x + ((size_t)(n * 32 + cb)) * 784;
        for (int i = lt; i < 2048; i += 224) {
            int c   = i >> 9;                // 0..3
            int rem = i & 511;
            int tr  = rem >> 5, col = rem & 31;
            int hh  = prow0 + tr - 1;        // image row
            int ww  = col - 1;               // image col
            float v = 0.f;
            if ((unsigned)hh < 28u && (unsigned)ww < 28u)
                v = xb[c * 784 + hh * 28 + ww];
            unsigned u = __float_as_uint(v);
            xt[team][c][tr][col] = ((unsigned long long)u << 32) | u;
        }
        __syncthreads();

        #pragma unroll 1
        for (int c = 0; c < 4; ++c) {
            #pragma unroll
            for (int dr = 0; dr < 3; ++dr) {
                const unsigned long long* xr = &xt[team][c][rloc + dr][c0];
                ulonglong2 xA = *(const ulonglong2*)xr;         // dup cols c0,c0+1
                ulonglong2 xB = *(const ulonglong2*)(xr + 2);   // dup cols c0+2,c0+3
                unsigned long long d0 = xA.x, d1 = xA.y, d2 = xB.x, d3 = xB.y;
                const int kb = (cb + c) * 9 + dr * 3;
                #pragma unroll
                for (int dq = 0; dq < 3; ++dq) {
                    ulonglong2 wv0 = nws2[(kb + dq) * 2];       // ocs 0-3
                    ulonglong2 wv1 = nws2[(kb + dq) * 2 + 1];   // ocs 4-7
                    unsigned long long e0 = (dq == 0) ? d0 : (dq == 1 ? d1 : d2);
                    unsigned long long e1 = (dq == 0) ? d1 : (dq == 1 ? d2 : d3);
                    adder2(acc[0][0], e0, wv0.x, mask);
                    adder2(acc[0][1], e0, wv0.y, mask);
                    adder2(acc[0][2], e0, wv1.x, mask);
                    adder2(acc[0][3], e0, wv1.y, mask);
                    adder2(acc[1][0], e1, wv0.x, mask);
                    adder2(acc[1][1], e1, wv0.y, mask);
                    adder2(acc[1][2], e1, wv1.x, mask);
                    adder2(acc[1][3], e1, wv1.y, mask);
                }
            }
        }
    }
    __syncthreads();

    // ---- team combine: B publishes, A accumulates (f32x2 adds) ----
    unsigned long long* comb = &xt[0][0][0][0];     // 196*8 u64 = 12.5KB of 32KB
    const int idx = wt * 28 + lid;                   // 0..195 when act
    if (team == 1 && act) {
        #pragma unroll
        for (int j = 0; j < 4; ++j) {
            comb[idx * 8 + j]     = acc[0][j];
            comb[idx * 8 + 4 + j] = acc[1][j];
        }
    }
    __syncthreads();
    if (team == 0 && act) {
        #pragma unroll
        for (int j = 0; j < 4; ++j) {
            acc[0][j] = add_f32x2(acc[0][j], comb[idx * 8 + j]);
            acc[1][j] = add_f32x2(acc[1][j], comb[idx * 8 + 4 + j]);
        }
    }

    // ---- unpack val[px][oc] (positive abs-sums; out = -val) ----
    float val[2][8];
    #pragma unroll
    for (int p = 0; p < 2; ++p)
        #pragma unroll
        for (int j = 0; j < 4; ++j) {
            val[p][2 * j]     = __uint_as_float((unsigned)(acc[p][j] & 0xFFFFFFFFu));
            val[p][2 * j + 1] = __uint_as_float((unsigned)(acc[p][j] >> 32));
        }

    // ---- block stats (team A): warp reduce 16 values, fold 7 warps ----
    {
        float sv[8], qv[8];
        const bool use = (team == 0) && act;
        #pragma unroll
        for (int j = 0; j < 8; ++j) {
            float a = use ? val[0][j] : 0.f;
            float b = use ? val[1][j] : 0.f;
            sv[j] = -(a + b);
            qv[j] = a * a + b * b;
        }
        #pragma unroll
        for (int d = 16; d > 0; d >>= 1) {
            #pragma unroll
            for (int j = 0; j < 8; ++j) {
                sv[j] += __shfl_down_sync(0xFFFFFFFFu, sv[j], d);
                qv[j] += __shfl_down_sync(0xFFFFFFFFu, qv[j], d);
            }
        }
        if (team == 0 && lid == 0) {
            #pragma unroll
            for (int j = 0; j < 8; ++j) {
                red[j][wt]     = sv[j];
                red[j + 8][wt] = qv[j];
            }
        }
    }
    __syncthreads();

    const int pidx = n * 2 + half;
    if (tid < 16) {
        float t = red[tid][0];
        #pragma unroll
        for (int u = 1; u < 7; ++u) t += red[tid][u];
        if (tid < 8) g_psum[(ocg * 8 + tid) * 16 + pidx] = t;
        else         g_psumsq[(ocg * 8 + (tid - 8)) * 16 + pidx] = t;
    }
    __syncthreads();

    // ---- replay-safe ticket barrier over 128 co-resident blocks ----
    if (tid == 0) {
        __threadfence();
        unsigned a = atomicAdd(&g_ctr, 1u);
        unsigned target = ((a >> 7) + 1u) << 7;
        while ((int)(*(volatile unsigned*)&g_ctr - target) < 0) __nanosleep(64);
        __threadfence();
    }
    __syncthreads();

    // ---- per-channel scale/bias: warps 0..7, 16 partials each ----
    if (wid < 8) {
        const int oc = ocg * 8 + wid;
        float ss = (lid < 16) ? *(volatile float*)&g_psum[oc * 16 + lid]   : 0.f;
        float qq = (lid < 16) ? *(volatile float*)&g_psumsq[oc * 16 + lid] : 0.f;
        #pragma unroll
        for (int d = 8; d > 0; d >>= 1) {
            ss += __shfl_down_sync(0xFFFFFFFFu, ss, d, 16);
            qq += __shfl_down_sync(0xFFFFFFFFu, qq, d, 16);
        }
        if (lid == 0) {
            float mean = ss * (1.f / 6272.f);
            float var  = qq * (1.f / 6272.f) - mean * mean;
            float sc = gamma[oc] * rsqrtf(var + 1e-5f);
            scb[wid] = make_float2(sc, beta[oc] - mean * sc);
        }
    }
    __syncthreads();

    // ---- normalize + store (team A): y = (-val)*sc + bi, float2 per oc ----
    if (team == 0 && act) {
        const int h = half * 14 + rloc;
        #pragma unroll
        for (int j = 0; j < 8; ++j) {
            float2 cb = scb[j];
            float* ob = out + ((size_t)(n * 64 + ocg * 8 + j)) * 784 + h * 28 + c0;
            *(float2*)ob = make_float2(fmaf(val[0][j], -cb.x, cb.y),
                                       fmaf(val[1][j], -cb.x, cb.y));
        }
    }
}

extern "C" void kernel_launch(void* const* d_in, const int* in_sizes, int n_in,
                              void* d_out, int out_size) {
    const float* x     = (const float*)d_in[0];  // [8,32,28,28]
    const float* W     = (const float*)d_in[1];  // [64,32,3,3]
    const float* gamma = (const float*)d_in[2];  // [64]
    const float* beta  = (const float*)d_in[3];  // [64]
    float* out = (float*)d_out;                  // [8,64,28,28]

    dim3 g1(2, 8, 8);
    fused_kernel<<<g1, 448>>>(x, W, gamma, beta, out);
}

// round 15
// speedup vs baseline: 1.3053x; 1.3053x over previous
#include <cuda_runtime.h>

// AdderConv + BatchNorm2d (training stats): x[8,32,28,28], W[64,32,3,3], pad=1.
// out[n,o,h,w] = -sum_k |x - w|, then per-channel BN (biased var, eps=1e-5).
//
// SINGLE kernel. Grid (16 oc-quads, 8 n, 2 channel-splits) = 256 blocks x 224
// thr (2 blocks/SM, 14 warps/SM). Thread = 4 consecutive pixels x 4 ocs.
// x via LDG from a padded (x,x)-duplicated u64 array (built in-kernel);
// w via broadcast LDS.128. Per (c,dr): 3 LDG.128 + 3 LDS.128 + 96 math insts
// -> LSU-lean (R11/R12 were bound at 3 LDS/k-iter ~ 25us chip-wide).
// ks=1 blocks write positive partials to scratch; ks=0 blocks combine, do
// stats, scale/bias, normalize, store. 3-phase replay-safe ticket barrier
// (pad -> combine -> stats), 256 tickets per phase.

__device__ __align__(16) unsigned long long g_xpad[8 * 32 * 30 * 32 + 64];
__device__ __align__(16) float g_part[16 * 8 * 4 * 784];   // [ocq][n][j][hw], 1.6MB
__device__ float g_psum[64 * 8];      // [oc][n]
__device__ float g_psumsq[64 * 8];
__device__ unsigned g_ctr;            // monotonic ticket counter (never reset)

__device__ __forceinline__ void adder2(unsigned long long& acc,
                                       unsigned long long xx,
                                       unsigned long long w,
                                       unsigned long long mask) {
    asm("{\n\t"
        ".reg .b64 t;\n\t"
        "add.rn.f32x2 t, %1, %2;\n\t"
        "and.b64 t, t, %3;\n\t"
        "add.rn.f32x2 %0, %0, t;\n\t"
        "}"
        : "+l"(acc) : "l"(xx), "l"(w), "l"(mask));
}

// All 256 blocks spin at every phase so each block contributes exactly one
// ticket per 256-window (phase boundaries at multiples of 256).
__device__ __forceinline__ void ticket_barrier_256() {
    __threadfence();
    unsigned a = atomicAdd(&g_ctr, 1u);
    unsigned target = ((a >> 8) + 1u) << 8;
    while ((int)(*(volatile unsigned*)&g_ctr - target) < 0) __nanosleep(64);
    __threadfence();
}

__global__ __launch_bounds__(224) void fused_kernel(
    const float* __restrict__ x, const float* __restrict__ W,
    const float* __restrict__ gamma, const float* __restrict__ beta,
    float* __restrict__ out)
{
    __shared__ __align__(16) ulonglong2 nws[144];   // this ks's 16 channels of w
    __shared__ float red[8][7];
    __shared__ float2 scb[4];

    const int ocq = blockIdx.x;   // 0..15 (ocs ocq*4 .. ocq*4+3)
    const int n   = blockIdx.y;   // 0..7
    const int ks  = blockIdx.z;   // 0..1 (channels ks*16 .. ks*16+15)
    const int tid = threadIdx.x;
    const int wid = tid >> 5;     // 0..6
    const int lid = tid & 31;
    const bool act = (lid < 28);
    int sr = lid / 7, cg = lid % 7;
    if (!act) { sr = 0; cg = 0; }
    const int row  = wid * 4 + sr;                  // 0..27
    const int col0 = cg * 4;                        // 0,4,...,24

    // ---- weights for this (ocq, ks): nws[kl] = {pack(-w0,-w1), pack(-w2,-w3)} ----
    const float* Wb = W + (ocq * 4) * 288;
    unsigned long long* nw64 = (unsigned long long*)nws;
    for (int i = tid; i < 288; i += 224) {
        int kl = i >> 1, pr = i & 1;
        int kg = ks * 144 + kl;
        unsigned lo = __float_as_uint(-Wb[(2 * pr) * 288 + kg]);
        unsigned hi = __float_as_uint(-Wb[(2 * pr + 1) * 288 + kg]);
        nw64[kl * 2 + pr] = ((unsigned long long)hi << 32) | lo;
    }

    // ---- padding: blocks ocq<4 build 4 channels (c0p = ks*16 + ocq*4) ----
    if (ocq < 4) {
        const int c0p = ks * 16 + ocq * 4;
        const float* xb = x + ((size_t)n * 32 + c0p) * 784;
        unsigned long long* dst = g_xpad + ((size_t)(n * 32 + c0p)) * 960;
        for (int i = tid; i < 3840; i += 224) {
            int lc = i / 960;
            int rem = i - lc * 960;
            int h = rem >> 5, w = rem & 31;
            float v = 0.f;
            if (h >= 1 && h <= 28 && w >= 1 && w <= 28)
                v = xb[lc * 784 + (h - 1) * 28 + (w - 1)];
            unsigned u = __float_as_uint(v);
            dst[lc * 960 + h * 32 + w] = ((unsigned long long)u << 32) | u;
        }
    }
    __threadfence();
    __syncthreads();
    if (tid == 0) ticket_barrier_256();   // B1: padding complete everywhere
    __syncthreads();

    // ---- conv mainloop: 16 channels, 4 px x 4 oc per thread ----
    const unsigned long long mask = 0x7FFFFFFF7FFFFFFFULL;
    unsigned long long a01[4] = {0ull, 0ull, 0ull, 0ull};   // (oc0,oc1) per px
    unsigned long long a23[4] = {0ull, 0ull, 0ull, 0ull};   // (oc2,oc3) per px

    const unsigned long long* xbase =
        g_xpad + (((size_t)(n * 32 + ks * 16)) * 30 + row) * 32 + col0;

    #pragma unroll 1
    for (int c = 0; c < 16; ++c) {
        #pragma unroll
        for (int dr = 0; dr < 3; ++dr) {
            const unsigned long long* xr = xbase + c * 960 + dr * 32;
            ulonglong2 xA = *(const ulonglong2*)(xr);       // dup q0,q1
            ulonglong2 xB = *(const ulonglong2*)(xr + 2);   // dup q2,q3
            ulonglong2 xC = *(const ulonglong2*)(xr + 4);   // dup q4,q5
            unsigned long long d[6] = {xA.x, xA.y, xB.x, xB.y, xC.x, xC.y};
            const int kb = c * 9 + dr * 3;
            #pragma unroll
            for (int dq = 0; dq < 3; ++dq) {
                ulonglong2 wv = nws[kb + dq];               // broadcast LDS.128
                adder2(a01[0], d[dq],     wv.x, mask);
                adder2(a23[0], d[dq],     wv.y, mask);
                adder2(a01[1], d[dq + 1], wv.x, mask);
                adder2(a23[1], d[dq + 1], wv.y, mask);
                adder2(a01[2], d[dq + 2], wv.x, mask);
                adder2(a23[2], d[dq + 2], wv.y, mask);
                adder2(a01[3], d[dq + 3], wv.x, mask);
                adder2(a23[3], d[dq + 3], wv.y, mask);
            }
        }
    }

    // ---- unpack 16 positive half-sums: val[px][oc] ----
    float val[4][4];
    #pragma unroll
    for (int p = 0; p < 4; ++p) {
        val[p][0] = __uint_as_float((unsigned)(a01[p] & 0xFFFFFFFFu));
        val[p][1] = __uint_as_float((unsigned)(a01[p] >> 32));
        val[p][2] = __uint_as_float((unsigned)(a23[p] & 0xFFFFFFFFu));
        val[p][3] = __uint_as_float((unsigned)(a23[p] >> 32));
    }

    // ---- combine across ks via scratch: ks=1 stores, ks=0 adds ----
    float* pbase = g_part + ((size_t)(ocq * 8 + n) * 4) * 784 + row * 28 + col0;
    if (ks == 1 && act) {
        #pragma unroll
        for (int j = 0; j < 4; ++j)
            *(float4*)(pbase + j * 784) =
                make_float4(val[0][j], val[1][j], val[2][j], val[3][j]);
    }
    __threadfence();
    __syncthreads();
    if (tid == 0) ticket_barrier_256();   // B2: partials visible
    __syncthreads();
    if (ks == 0 && act) {
        #pragma unroll
        for (int j = 0; j < 4; ++j) {
            float4 pv = *(const float4*)(pbase + j * 784);
            val[0][j] += pv.x; val[1][j] += pv.y;
            val[2][j] += pv.z; val[3][j] += pv.w;
        }
    }

    // ---- block stats (ks=0 covers the full image for its 4 ocs) ----
    float sv[4], qv[4];
    #pragma unroll
    for (int j = 0; j < 4; ++j) {
        float s = 0.f, q = 0.f;
        #pragma unroll
        for (int p = 0; p < 4; ++p) {
            float v = val[p][j];
            s -= v;              // out value is -val
            q += v * v;
        }
        sv[j] = act ? s : 0.f;
        qv[j] = act ? q : 0.f;
    }
    #pragma unroll
    for (int dd = 16; dd > 0; dd >>= 1) {
        #pragma unroll
        for (int j = 0; j < 4; ++j) {
            sv[j] += __shfl_down_sync(0xFFFFFFFFu, sv[j], dd);
            qv[j] += __shfl_down_sync(0xFFFFFFFFu, qv[j], dd);
        }
    }
    if (lid == 0) {
        #pragma unroll
        for (int j = 0; j < 4; ++j) {
            red[j][wid]     = sv[j];
            red[4 + j][wid] = qv[j];
        }
    }
    __syncthreads();
    if (tid < 8 && ks == 0) {
        float t = red[tid][0];
        #pragma unroll
        for (int u = 1; u < 7; ++u) t += red[tid][u];
        if (tid < 4) g_psum[(ocq * 4 + tid) * 8 + n] = t;
        else         g_psumsq[(ocq * 4 + (tid - 4)) * 8 + n] = t;
    }
    __threadfence();
    __syncthreads();
    if (tid == 0) ticket_barrier_256();   // B3: all (n,oc) stats published
    __syncthreads();

    if (ks == 1) return;                  // done (already contributed B3 ticket)

    // ---- per-channel scale/bias: 32 threads fold the 8 batch partials ----
    if (tid < 32) {
        const int j = tid >> 3, nn = tid & 7;
        const int oc = ocq * 4 + j;
        float ss = *(volatile float*)&g_psum[oc * 8 + nn];
        float qq = *(volatile float*)&g_psumsq[oc * 8 + nn];
        #pragma unroll
        for (int dd = 4; dd > 0; dd >>= 1) {
            ss += __shfl_down_sync(0xFFFFFFFFu, ss, dd, 8);
            qq += __shfl_down_sync(0xFFFFFFFFu, qq, dd, 8);
        }
        if (nn == 0) {
            float mean = ss * (1.f / 6272.f);
            float var  = qq * (1.f / 6272.f) - mean * mean;
            float sc = gamma[oc] * rsqrtf(var + 1e-5f);
            scb[j] = make_float2(sc, beta[oc] - mean * sc);
        }
    }
    __syncthreads();

    // ---- normalize in registers, float4 store per oc ----
    if (act) {
        #pragma unroll
        for (int j = 0; j < 4; ++j) {
            float2 cb = scb[j];
            float* ob = out + ((size_t)(n * 64 + ocq * 4 + j)) * 784 + row * 28 + col0;
            *(float4*)ob = make_float4(fmaf(val[0][j], -cb.x, cb.y),
                                       fmaf(val[1][j], -cb.x, cb.y),
                                       fmaf(val[2][j], -cb.x, cb.y),
                                       fmaf(val[3][j], -cb.x, cb.y));
        }
    }
}

extern "C" void kernel_launch(void* const* d_in, const int* in_sizes, int n_in,
                              void* d_out, int out_size) {
    const float* x     = (const float*)d_in[0];  // [8,32,28,28]
    const float* W     = (const float*)d_in[1];  // [64,32,3,3]
    const float* gamma = (const float*)d_in[2];  // [64]
    const float* beta  = (const float*)d_in[3];  // [64]
    float* out = (float*)d_out;                  // [8,64,28,28]

    dim3 g1(16, 8, 2);
    fused_kernel<<<g1, 224>>>(x, W, gamma, beta, out);
}

// round 16
// speedup vs baseline: 1.9000x; 1.4556x over previous
#include <cuda_runtime.h>

// AdderConv + BatchNorm2d (training stats): x[8,32,28,28], W[64,32,3,3], pad=1.
// out[n,o,h,w] = -sum_k |x - w|, then per-channel BN (biased var, eps=1e-5).
//
// SINGLE fused kernel (R11 skeleton): grid (4 spatial 14x14 tiles, 8 oc-groups,
// 8 n) = 256 blocks x 256 thr, 41KB smem, all co-resident (2/SM max).
// SCALAR mainloop: acc[j] += fabsf(xv + nw[j]) -> 2 FADD each (diff, then
// acc with |src| modifier). No packed 64-bit ops, no LOP3, no asm: pure-fma
// stream whose rt-2 floor (~35 cyc/warp-k-iter) is actually achievable,
// unlike the packed version's theoretically-lower-but-unreachable floor.
// Epilogue: block stats, replay-safe ticket barrier over the 256 co-resident
// blocks, per-channel scale/bias, in-register normalize, single write.

__device__ float g_psum[64 * 32];     // [oc][pidx], pidx = n*4 + s
__device__ float g_psumsq[64 * 32];
__device__ unsigned g_ctr;            // monotonic ticket counter (never reset)

__global__ __launch_bounds__(256) void fused_kernel(
    const float* __restrict__ x, const float* __restrict__ W,
    const float* __restrict__ gamma, const float* __restrict__ beta,
    float* __restrict__ out)
{
    __shared__ __align__(16) float xs[32 * 16 * 16];   // 32KB
    __shared__ __align__(16) float nws[288 * 8];       // 9KB negated w, k-major
    __shared__ float red[16][8];                       // warp partials
    __shared__ float2 scb[8];                          // per-oc {scale, bias}

    const int s   = blockIdx.x;   // spatial tile 0..3
    const int ocg = blockIdx.y;   // 0..7 (8 output channels each)
    const int n   = blockIdx.z;   // 0..7
    const int th  = (s >> 1) * 14;
    const int tw  = (s & 1) * 14;
    const int tid = threadIdx.x;
    const int wid = tid >> 5;
    const int lid = tid & 31;

    // ---- prologue: x tile (zero halo) + negated weights ----
    const float* xb = x + n * (32 * 28 * 28);
    #pragma unroll
    for (int i = tid; i < 32 * 256; i += 256) {
        int c = i >> 8, cell = i & 255;
        int r = cell >> 4, col = cell & 15;
        int gh = th - 1 + r, gw = tw - 1 + col;
        float v = 0.f;
        if ((unsigned)gh < 28u && (unsigned)gw < 28u)
            v = xb[c * 784 + gh * 28 + gw];
        xs[i] = v;
    }
    const float* Wb = W + ocg * (8 * 288);
    #pragma unroll
    for (int i = tid; i < 8 * 288; i += 256) {
        int o = i & 7, k = i >> 3;
        nws[k * 8 + o] = -Wb[o * 288 + k];
    }
    __syncthreads();

    // ---- scalar mainloop: acc[j] += fabsf(xv + nw[j]) ----
    float acc0 = 0.f, acc1 = 0.f, acc2 = 0.f, acc3 = 0.f;
    float acc4 = 0.f, acc5 = 0.f, acc6 = 0.f, acc7 = 0.f;
    if (tid < 196) {
        const int ph = tid / 14;
        const int pw = tid - ph * 14;
        const float* xp = xs + ph * 16 + pw;

        #pragma unroll 1
        for (int c = 0; c < 32; ++c) {
            const float* xc = xp + c * 256;
            const float4* wk = (const float4*)(nws + c * 9 * 8);
            #pragma unroll
            for (int r = 0; r < 3; ++r) {
                #pragma unroll
                for (int q = 0; q < 3; ++q) {
                    float xv = xc[r * 16 + q];
                    float4 wa = wk[(r * 3 + q) * 2];
                    float4 wb = wk[(r * 3 + q) * 2 + 1];
                    acc0 += fabsf(xv + wa.x);
                    acc1 += fabsf(xv + wa.y);
                    acc2 += fabsf(xv + wa.z);
                    acc3 += fabsf(xv + wa.w);
                    acc4 += fabsf(xv + wb.x);
                    acc5 += fabsf(xv + wb.y);
                    acc6 += fabsf(xv + wb.z);
                    acc7 += fabsf(xv + wb.w);
                }
            }
        }
    }

    float val[8] = {acc0, acc1, acc2, acc3, acc4, acc5, acc6, acc7};

    // ---- block stats: warp shfl reduce, 8-warp fold ----
    float sv[8], qv[8];
    #pragma unroll
    for (int j = 0; j < 8; ++j) {
        float v = (tid < 196) ? val[j] : 0.f;
        sv[j] = -v;            // out value is -val
        qv[j] = v * v;
    }
    #pragma unroll
    for (int d = 16; d > 0; d >>= 1) {
        #pragma unroll
        for (int j = 0; j < 8; ++j) {
            sv[j] += __shfl_down_sync(0xFFFFFFFFu, sv[j], d);
            qv[j] += __shfl_down_sync(0xFFFFFFFFu, qv[j], d);
        }
    }
    if (lid == 0) {
        #pragma unroll
        for (int j = 0; j < 8; ++j) {
            red[j][wid]     = sv[j];
            red[j + 8][wid] = qv[j];
        }
    }
    __syncthreads();

    const int pidx = n * 4 + s;
    if (tid < 16) {
        float t = red[tid][0];
        #pragma unroll
        for (int u = 1; u < 8; ++u) t += red[tid][u];
        if (tid < 8) g_psum[(ocg * 8 + tid) * 32 + pidx] = t;
        else         g_psumsq[(ocg * 8 + (tid - 8)) * 32 + pidx] = t;
    }
    __syncthreads();

    // ---- replay-safe ticket barrier over the 256 co-resident blocks ----
    if (tid == 0) {
        __threadfence();
        unsigned arrival = atomicAdd(&g_ctr, 1u);
        unsigned target = ((arrival >> 8) + 1u) << 8;   // this launch's 256th ticket
        while ((int)(*(volatile unsigned*)&g_ctr - target) < 0) __nanosleep(64);
        __threadfence();
    }
    __syncthreads();

    // ---- per-channel stats: warp w folds oc (ocg*8+w)'s 32 partials ----
    {
        const int oc = ocg * 8 + wid;
        float ss = *(volatile float*)&g_psum[oc * 32 + lid];
        float qq = *(volatile float*)&g_psumsq[oc * 32 + lid];
        #pragma unroll
        for (int d = 16; d > 0; d >>= 1) {
            ss += __shfl_down_sync(0xFFFFFFFFu, ss, d);
            qq += __shfl_down_sync(0xFFFFFFFFu, qq, d);
        }
        if (lid == 0) {
            float mean = ss * (1.f / 6272.f);
            float var  = qq * (1.f / 6272.f) - mean * mean;
            float sc = gamma[oc] * rsqrtf(var + 1e-5f);
            scb[wid] = make_float2(sc, beta[oc] - mean * sc);
        }
    }
    __syncthreads();

    // ---- normalize in registers, single global write ----
    if (tid < 196) {
        const int ph = tid / 14;
        const int pw = tid - ph * 14;
        const int gh = th + ph, gw = tw + pw;
        float* ob = out + (n * 64 + ocg * 8) * 784 + gh * 28 + gw;
        #pragma unroll
        for (int j = 0; j < 8; ++j) {
            float2 c = scb[j];
            ob[j * 784] = fmaf(val[j], -c.x, c.y);   // y = (-val)*sc + bi
        }
    }
}

extern "C" void kernel_launch(void* const* d_in, const int* in_sizes, int n_in,
                              void* d_out, int out_size) {
    const float* x     = (const float*)d_in[0];  // [8,32,28,28]
    const float* W     = (const float*)d_in[1];  // [64,32,3,3]
    const float* gamma = (const float*)d_in[2];  // [64]
    const float* beta  = (const float*)d_in[3];  // [64]
    float* out = (float*)d_out;                  // [8,64,28,28]

    dim3 g1(4, 8, 8);
    fused_kernel<<<g1, 256>>>(x, W, gamma, beta, out);
}